// round 2
// baseline (speedup 1.0000x reference)
#include <cuda_runtime.h>
#include <cuda_bf16.h>
#include <stdint.h>

// GCN 2-layer:  out = GCN2( relu(GCN1(x)) )
// GCN(x) with self loops, symmetric norm:
//   g   = (x @ W) * dinv[row]          (dinv = rsqrt(indeg+1))
//   acc[d] = sum_{e: dst=d} g[src_e] + g[d]
//   y   = dinv[d] * acc[d] + b
//
// Scratch lives in __device__ globals (no allocation allowed).

#define NMAX 100096
#define F_IN 128
#define H1 32
#define H2 16

__device__ float g_dinv[NMAX];
__device__ float g_g1[NMAX * H1];
__device__ float g_acc1[NMAX * H1];
__device__ float g_g2[NMAX * H2];

// ---------------------------------------------------------------- degree ----
__global__ void k_init_deg(int n) {
    int i = blockIdx.x * blockDim.x + threadIdx.x;
    if (i < n) g_dinv[i] = 1.0f;  // self loop
}

__global__ void k_count_deg(const int* __restrict__ dst, int E) {
    int e = blockIdx.x * blockDim.x + threadIdx.x;
    if (e < E) atomicAdd(&g_dinv[dst[e]], 1.0f);  // no-return -> RED
}

__global__ void k_rsqrt_deg(int n) {
    int i = blockIdx.x * blockDim.x + threadIdx.x;
    if (i < n) g_dinv[i] = rsqrtf(g_dinv[i]);
}

// ------------------------------------------------------------- layer 1 ------
// warp-per-row GEMM: g1[row][f] = dinv[row] * sum_k x[row][k] * W1[k][f]
// also initializes acc1 = g1 (self-loop term).
__global__ void k_gemm1(const float* __restrict__ x, const float* __restrict__ W1, int n) {
    __shared__ float Ws[F_IN * H1];   // 16 KB
    __shared__ float xs[8][F_IN];     // 4 KB
    int tid = threadIdx.x;            // 256 threads = 8 warps
    for (int i = tid; i < F_IN * H1; i += 256) Ws[i] = W1[i];

    int row0 = blockIdx.x * 8;
    // cooperative, coalesced load of 8 rows of x
    for (int i = tid; i < 8 * F_IN; i += 256) {
        int r = i >> 7, c = i & 127;
        int row = row0 + r;
        xs[r][c] = (row < n) ? x[row * F_IN + c] : 0.0f;
    }
    __syncthreads();

    int warp = tid >> 5, lane = tid & 31;
    int row = row0 + warp;
    if (row >= n) return;

    const float4* xr = (const float4*)xs[warp];
    float acc = 0.0f;
#pragma unroll
    for (int k4 = 0; k4 < F_IN / 4; k4++) {
        float4 xv = xr[k4];  // smem broadcast (all lanes same addr)
        acc = fmaf(xv.x, Ws[(k4 * 4 + 0) * H1 + lane], acc);
        acc = fmaf(xv.y, Ws[(k4 * 4 + 1) * H1 + lane], acc);
        acc = fmaf(xv.z, Ws[(k4 * 4 + 2) * H1 + lane], acc);
        acc = fmaf(xv.w, Ws[(k4 * 4 + 3) * H1 + lane], acc);
    }
    float v = acc * g_dinv[row];
    g_g1[row * H1 + lane]   = v;
    g_acc1[row * H1 + lane] = v;
}

// per-edge scatter: acc1[dst] += g1[src]  (32 floats = 8 x red.v4)
__global__ void k_scatter1(const int* __restrict__ src, const int* __restrict__ dst, int E) {
    long long tid = (long long)blockIdx.x * blockDim.x + threadIdx.x;
    if (tid >= (long long)E * 8) return;
    int e = (int)(tid >> 3), c = (int)(tid & 7);
    int s = __ldg(&src[e]);
    int d = __ldg(&dst[e]);
    float4 v = ((const float4*)(g_g1 + s * H1))[c];
    float* p = g_acc1 + d * H1 + c * 4;
    asm volatile("red.global.add.v4.f32 [%0], {%1,%2,%3,%4};"
                 :: "l"(p), "f"(v.x), "f"(v.y), "f"(v.z), "f"(v.w) : "memory");
}

// epilogue layer1 + GEMM2 fused:
//   h[f]  = relu(dinv*acc1 + b1[f])         (lane f holds h[f])
//   g2[j] = dinv * sum_k h[k]*W2[k][j]      (via warp shuffles)
// writes g2 and initializes out = g2 (self-loop term of layer 2).
__global__ void k_finish1_gemm2(const float* __restrict__ W2, const float* __restrict__ b1,
                                float* __restrict__ out, int n) {
    __shared__ float W2s[H1 * H2];  // 2 KB
    __shared__ float b1s[H1];
    int tid = threadIdx.x;  // 256
    for (int i = tid; i < H1 * H2; i += 256) W2s[i] = W2[i];
    if (tid < H1) b1s[tid] = b1[tid];
    __syncthreads();

    int warp = tid >> 5, lane = tid & 31;
    int row = blockIdx.x * 8 + warp;
    if (row >= n) return;

    float di = g_dinv[row];
    float h = fmaxf(fmaf(di, g_acc1[row * H1 + lane], b1s[lane]), 0.0f);

    float acc = 0.0f;
    int j = lane & 15;
#pragma unroll
    for (int k = 0; k < H1; k++) {
        float v = __shfl_sync(0xffffffffu, h, k);
        acc = fmaf(v, W2s[k * H2 + j], acc);
    }
    if (lane < H2) {
        float g = acc * di;
        g_g2[row * H2 + lane] = g;
        out[row * H2 + lane]  = g;
    }
}

// per-edge scatter layer 2: out[dst] += g2[src]  (16 floats = 4 x red.v4)
__global__ void k_scatter2(const int* __restrict__ src, const int* __restrict__ dst,
                           float* __restrict__ out, int E) {
    long long tid = (long long)blockIdx.x * blockDim.x + threadIdx.x;
    if (tid >= (long long)E * 4) return;
    int e = (int)(tid >> 2), c = (int)(tid & 3);
    int s = __ldg(&src[e]);
    int d = __ldg(&dst[e]);
    float4 v = ((const float4*)(g_g2 + s * H2))[c];
    float* p = out + d * H2 + c * 4;
    asm volatile("red.global.add.v4.f32 [%0], {%1,%2,%3,%4};"
                 :: "l"(p), "f"(v.x), "f"(v.y), "f"(v.z), "f"(v.w) : "memory");
}

__global__ void k_finish2(float* __restrict__ out, const float* __restrict__ b2, int total) {
    int i = blockIdx.x * blockDim.x + threadIdx.x;
    if (i < total) {
        out[i] = fmaf(g_dinv[i >> 4], out[i], b2[i & 15]);
    }
}

// ------------------------------------------------------------------ host ----
extern "C" void kernel_launch(void* const* d_in, const int* in_sizes, int n_in,
                              void* d_out, int out_size) {
    const float* x  = (const float*)d_in[0];
    const int*   ei = (const int*)d_in[1];
    const float* W1 = (const float*)d_in[2];
    const float* b1 = (const float*)d_in[3];
    const float* W2 = (const float*)d_in[4];
    const float* b2 = (const float*)d_in[5];
    float* out = (float*)d_out;

    int n = in_sizes[0] / F_IN;   // 100000
    int E = in_sizes[1] / 2;      // 3200000
    const int* src = ei;
    const int* dst = ei + E;

    k_init_deg<<<(n + 255) / 256, 256>>>(n);
    k_count_deg<<<(E + 255) / 256, 256>>>(dst, E);
    k_rsqrt_deg<<<(n + 255) / 256, 256>>>(n);

    k_gemm1<<<(n + 7) / 8, 256>>>(x, W1, n);
    k_scatter1<<<(int)(((long long)E * 8 + 255) / 256), 256>>>(src, dst, E);
    k_finish1_gemm2<<<(n + 7) / 8, 256>>>(W2, b1, out, n);
    k_scatter2<<<(int)(((long long)E * 4 + 255) / 256), 256>>>(src, dst, out, E);
    k_finish2<<<(n * H2 + 255) / 256, 256>>>(out, b2, n * H2);
}

// round 3
// speedup vs baseline: 1.2526x; 1.2526x over previous
#include <cuda_runtime.h>
#include <cuda_bf16.h>
#include <stdint.h>

// GCN 2-layer:  out = GCN2( relu(GCN1(x)) )
//   g   = (x @ W) * dinv[row]          (dinv = rsqrt(indeg+1))
//   acc[d] = sum_{e: dst=d} g[src_e] + g[d]
//   y   = dinv[d] * acc[d] + b

#define NMAX 100096
#define F_IN 128
#define H1 32
#define H2 16

__device__ float g_dinv[NMAX];
__device__ float g_g1[NMAX * H1];
__device__ float g_acc1[NMAX * H1];
__device__ float g_g2[NMAX * H2];

// ---------------------------------------------------------------- degree ----
__global__ void k_init_deg(int n) {
    int i = blockIdx.x * blockDim.x + threadIdx.x;
    if (i < n) g_dinv[i] = 1.0f;  // self loop
}

__global__ void k_count_deg(const int* __restrict__ dst, int E) {
    int e = blockIdx.x * blockDim.x + threadIdx.x;
    if (e < E) atomicAdd(&g_dinv[dst[e]], 1.0f);  // no-return -> RED
}

__global__ void k_rsqrt_deg(int n) {
    int i = blockIdx.x * blockDim.x + threadIdx.x;
    if (i < n) g_dinv[i] = rsqrtf(g_dinv[i]);
}

// ------------------------------------------------------------- layer 1 ------
// Register-tiled GEMM: each thread computes 8 rows x 4 cols.
// Warp = 4 rowgroups (8 rows each) x 8 colgroups (4 cols each) -> 32 rows.
// Block = 8 warps -> 256 rows. W1 staged in smem, read as float4 and held in
// registers across the 8 rows (crossbar bytes/FMA ~0.5 instead of ~5).
__global__ void __launch_bounds__(256) k_gemm1(const float* __restrict__ x,
                                               const float* __restrict__ W1, int n) {
    __shared__ float Ws[F_IN * H1];   // 16 KB, k-major rows of 32
    int tid = threadIdx.x;
    for (int i = tid; i < F_IN * H1; i += 256) Ws[i] = W1[i];
    __syncthreads();

    int lane = tid & 31, warp = tid >> 5;
    int c0 = (lane & 7) * 4;          // column offset (colgroup)
    int rg = lane >> 3;               // rowgroup within warp (0..3)
    int rowbase = blockIdx.x * 256 + warp * 32 + rg * 8;

    float acc[8][4] = {};
#pragma unroll
    for (int k4 = 0; k4 < F_IN; k4 += 4) {
        float4 w0 = *(const float4*)&Ws[(k4 + 0) * H1 + c0];
        float4 w1 = *(const float4*)&Ws[(k4 + 1) * H1 + c0];
        float4 w2 = *(const float4*)&Ws[(k4 + 2) * H1 + c0];
        float4 w3 = *(const float4*)&Ws[(k4 + 3) * H1 + c0];
#pragma unroll
        for (int r = 0; r < 8; r++) {
            int row = rowbase + r;
            row = row < n ? row : n - 1;  // clamp (tail block only)
            float4 xv = __ldg((const float4*)&x[(size_t)row * F_IN + k4]);
            acc[r][0] = fmaf(xv.x, w0.x, acc[r][0]);
            acc[r][1] = fmaf(xv.x, w0.y, acc[r][1]);
            acc[r][2] = fmaf(xv.x, w0.z, acc[r][2]);
            acc[r][3] = fmaf(xv.x, w0.w, acc[r][3]);
            acc[r][0] = fmaf(xv.y, w1.x, acc[r][0]);
            acc[r][1] = fmaf(xv.y, w1.y, acc[r][1]);
            acc[r][2] = fmaf(xv.y, w1.z, acc[r][2]);
            acc[r][3] = fmaf(xv.y, w1.w, acc[r][3]);
            acc[r][0] = fmaf(xv.z, w2.x, acc[r][0]);
            acc[r][1] = fmaf(xv.z, w2.y, acc[r][1]);
            acc[r][2] = fmaf(xv.z, w2.z, acc[r][2]);
            acc[r][3] = fmaf(xv.z, w2.w, acc[r][3]);
            acc[r][0] = fmaf(xv.w, w3.x, acc[r][0]);
            acc[r][1] = fmaf(xv.w, w3.y, acc[r][1]);
            acc[r][2] = fmaf(xv.w, w3.z, acc[r][2]);
            acc[r][3] = fmaf(xv.w, w3.w, acc[r][3]);
        }
    }

#pragma unroll
    for (int r = 0; r < 8; r++) {
        int row = rowbase + r;
        if (row < n) {
            float di = g_dinv[row];
            float4 v = make_float4(acc[r][0] * di, acc[r][1] * di,
                                   acc[r][2] * di, acc[r][3] * di);
            *(float4*)&g_g1[row * H1 + c0]   = v;
            *(float4*)&g_acc1[row * H1 + c0] = v;
        }
    }
}

// per-edge scatter: acc1[dst] += g1[src]  (32 floats = 8 x red.v4)
__global__ void k_scatter1(const int* __restrict__ src, const int* __restrict__ dst, int E) {
    long long tid = (long long)blockIdx.x * blockDim.x + threadIdx.x;
    if (tid >= (long long)E * 8) return;
    int e = (int)(tid >> 3), c = (int)(tid & 7);
    int s = __ldg(&src[e]);
    int d = __ldg(&dst[e]);
    float4 v = ((const float4*)(g_g1 + s * H1))[c];
    float* p = g_acc1 + d * H1 + c * 4;
    asm volatile("red.global.add.v4.f32 [%0], {%1,%2,%3,%4};"
                 :: "l"(p), "f"(v.x), "f"(v.y), "f"(v.z), "f"(v.w) : "memory");
}

// epilogue layer1 + GEMM2 fused (warp shuffles), writes g2 and out self-loop.
__global__ void k_finish1_gemm2(const float* __restrict__ W2, const float* __restrict__ b1,
                                float* __restrict__ out, int n) {
    __shared__ float W2s[H1 * H2];  // 2 KB
    __shared__ float b1s[H1];
    int tid = threadIdx.x;  // 256
    for (int i = tid; i < H1 * H2; i += 256) W2s[i] = W2[i];
    if (tid < H1) b1s[tid] = b1[tid];
    __syncthreads();

    int warp = tid >> 5, lane = tid & 31;
    int row = blockIdx.x * 8 + warp;
    if (row >= n) return;

    float di = g_dinv[row];
    float h = fmaxf(fmaf(di, g_acc1[row * H1 + lane], b1s[lane]), 0.0f);

    float acc = 0.0f;
    int j = lane & 15;
#pragma unroll
    for (int k = 0; k < H1; k++) {
        float v = __shfl_sync(0xffffffffu, h, k);
        acc = fmaf(v, W2s[k * H2 + j], acc);
    }
    if (lane < H2) {
        float g = acc * di;
        g_g2[row * H2 + lane] = g;
        out[row * H2 + lane]  = g;
    }
}

// per-edge scatter layer 2: out[dst] += g2[src]  (16 floats = 4 x red.v4)
__global__ void k_scatter2(const int* __restrict__ src, const int* __restrict__ dst,
                           float* __restrict__ out, int E) {
    long long tid = (long long)blockIdx.x * blockDim.x + threadIdx.x;
    if (tid >= (long long)E * 4) return;
    int e = (int)(tid >> 2), c = (int)(tid & 3);
    int s = __ldg(&src[e]);
    int d = __ldg(&dst[e]);
    float4 v = ((const float4*)(g_g2 + s * H2))[c];
    float* p = out + d * H2 + c * 4;
    asm volatile("red.global.add.v4.f32 [%0], {%1,%2,%3,%4};"
                 :: "l"(p), "f"(v.x), "f"(v.y), "f"(v.z), "f"(v.w) : "memory");
}

__global__ void k_finish2(float* __restrict__ out, const float* __restrict__ b2, int total) {
    int i = blockIdx.x * blockDim.x + threadIdx.x;
    if (i < total) {
        out[i] = fmaf(g_dinv[i >> 4], out[i], b2[i & 15]);
    }
}

// ------------------------------------------------------------------ host ----
extern "C" void kernel_launch(void* const* d_in, const int* in_sizes, int n_in,
                              void* d_out, int out_size) {
    const float* x  = (const float*)d_in[0];
    const int*   ei = (const int*)d_in[1];
    const float* W1 = (const float*)d_in[2];
    const float* b1 = (const float*)d_in[3];
    const float* W2 = (const float*)d_in[4];
    const float* b2 = (const float*)d_in[5];
    float* out = (float*)d_out;

    int n = in_sizes[0] / F_IN;   // 100000
    int E = in_sizes[1] / 2;      // 3200000
    const int* src = ei;
    const int* dst = ei + E;

    k_init_deg<<<(n + 255) / 256, 256>>>(n);
    k_count_deg<<<(E + 255) / 256, 256>>>(dst, E);
    k_rsqrt_deg<<<(n + 255) / 256, 256>>>(n);

    k_gemm1<<<(n + 255) / 256, 256>>>(x, W1, n);
    k_scatter1<<<(int)(((long long)E * 8 + 255) / 256), 256>>>(src, dst, E);
    k_finish1_gemm2<<<(n + 7) / 8, 256>>>(W2, b1, out, n);
    k_scatter2<<<(int)(((long long)E * 4 + 255) / 256), 256>>>(src, dst, out, E);
    k_finish2<<<(n * H2 + 255) / 256, 256>>>(out, b2, n * H2);
}